// round 1
// baseline (speedup 1.0000x reference)
#include <cuda_runtime.h>
#include <cuda_fp16.h>

// ============================================================================
// FeatureSharingLayer: 5 chained 128x128 GEMMs over M = 262144 rows.
//   Wc    = out_w @ Wv (fold of in_proj V + out proj), bc = out_w@bv + out_b
//   W1eff = sum of 8 column-chunks of fuse_w1 (tile() collapse)
//   A    = tf   @ Wc^T    + bc
//   h    = relu(A @ W1eff^T + b1)
//   Ahat = h    @ W2^T    + b2 + A
//   h2   = relu(Ahat @ W3^T + b3)
//   out  = h2   @ W4^T    + b4 + tf
// fp16 HMMA (mma.sync m16n8k16) with fp32 accumulation; residuals fp32-exact.
// ============================================================================

#define DIM 128
#define M_TOTAL (32768 * 8)      // 262144
#define N_TILES (M_TOTAL / 128)  // 2048
#define N_STAGES 5
#define GRID_MAIN 152            // GB300: 152 SMs, persistent 1 CTA/SM

// Scratch (device globals: no allocation allowed)
__device__ float   g_W[N_STAGES][DIM * DIM];      // dense fp32 intermediates
__device__ float   g_bias[N_STAGES][DIM];
__device__ __half2 g_frag[N_STAGES * 8 * 16 * 32 * 2];  // B-fragment order, 160KB

// Dynamic smem layout
#define SMEM_FRAG_BYTES (N_STAGES * 8 * 16 * 32 * 2 * 4)  // 163840
#define SMEM_BIAS_BYTES (N_STAGES * DIM * 4)              // 2560
#define SMEM_TOTAL (SMEM_FRAG_BYTES + SMEM_BIAS_BYTES)    // 166400

// ----------------------------------------------------------------------------
// Prologue 1: build dense folded weights + biases (trivial cost)
// grid (128, 5), block 128. blockIdx.x = n (output row), blockIdx.y = stage.
// ----------------------------------------------------------------------------
__global__ void precompute_dense(
    const float* __restrict__ ipw, const float* __restrict__ ipb,
    const float* __restrict__ ow,  const float* __restrict__ ob,
    const float* __restrict__ fw1, const float* __restrict__ fb1,
    const float* __restrict__ fw2, const float* __restrict__ fb2,
    const float* __restrict__ uw1, const float* __restrict__ ub1,
    const float* __restrict__ uw2, const float* __restrict__ ub2)
{
    int n = blockIdx.x, s = blockIdx.y, k = threadIdx.x;
    float v = 0.f;
    if (s == 0) {
        // Wc[n][k] = sum_j out_w[n][j] * Wv[j][k],  Wv = in_proj_w rows 256..383
        for (int j = 0; j < 128; j++)
            v += ow[n * 128 + j] * ipw[(256 + j) * 128 + k];
    } else if (s == 1) {
        for (int t = 0; t < 8; t++) v += fw1[n * 1024 + t * 128 + k];
    } else if (s == 2) v = fw2[n * 128 + k];
    else if (s == 3) v = uw1[n * 128 + k];
    else              v = uw2[n * 128 + k];
    g_W[s][n * 128 + k] = v;

    if (k == 0) {
        float b;
        if (s == 0) {
            b = ob[n];
            for (int j = 0; j < 128; j++) b += ow[n * 128 + j] * ipb[256 + j];
        } else if (s == 1) b = fb1[n];
        else if (s == 2)   b = fb2[n];
        else if (s == 3)   b = ub1[n];
        else               b = ub2[n];
        g_bias[s][n] = b;
    }
}

// ----------------------------------------------------------------------------
// Prologue 2: pack weights into exact m16n8k16 B-fragment order (fp16).
// Layout: [stage][kb(8)][nb(16)][lane(32)] -> 2 half2 (one uint2 per LDS).
// B[k][n] = W[n][k]; thread lane (g = lane/4, t = lane%4) holds:
//   reg0 = (W[n][k0], W[n][k0+1]),  reg1 = (W[n][k0+8], W[n][k0+9])
// with n = nb*8+g, k0 = kb*16 + 2t.
// ----------------------------------------------------------------------------
__global__ void pack_frags()
{
    int idx = blockIdx.x * 256 + threadIdx.x;       // 0 .. 20479
    if (idx >= N_STAGES * 8 * 16 * 32) return;
    int lane = idx & 31;
    int nb   = (idx >> 5) & 15;
    int kb   = (idx >> 9) & 7;
    int s    = idx >> 12;
    int g = lane >> 2, t = lane & 3;
    int n = nb * 8 + g, k0 = kb * 16 + 2 * t;
    const float* W = g_W[s];
    g_frag[idx * 2 + 0] = __floats2half2_rn(W[n * 128 + k0],     W[n * 128 + k0 + 1]);
    g_frag[idx * 2 + 1] = __floats2half2_rn(W[n * 128 + k0 + 8], W[n * 128 + k0 + 9]);
}

// ----------------------------------------------------------------------------
// Main fused kernel
// ----------------------------------------------------------------------------
__device__ __forceinline__ unsigned pack_h2(float x, float y)
{
    __half2 h = __floats2half2_rn(x, y);
    return *reinterpret_cast<unsigned*>(&h);
}

__device__ __forceinline__ void mma16816(float c[4], const unsigned a[4],
                                         unsigned b0, unsigned b1)
{
    asm volatile(
        "mma.sync.aligned.m16n8k16.row.col.f32.f16.f16.f32 "
        "{%0,%1,%2,%3}, {%4,%5,%6,%7}, {%8,%9}, {%0,%1,%2,%3};\n"
        : "+f"(c[0]), "+f"(c[1]), "+f"(c[2]), "+f"(c[3])
        : "r"(a[0]), "r"(a[1]), "r"(a[2]), "r"(a[3]), "r"(b0), "r"(b1));
}

// One full 16x128 x 128x128 stage GEMM for this warp.
__device__ __forceinline__ void run_gemm(const uint2* __restrict__ sFrag, int s,
                                         int lane, const unsigned a[8][4],
                                         float c[16][4])
{
#pragma unroll
    for (int kb = 0; kb < 8; kb++) {
#pragma unroll
        for (int nb = 0; nb < 16; nb++) {
            uint2 b = sFrag[((s * 8 + kb) * 16 + nb) * 32 + lane];
            mma16816(c[nb], a[kb], b.x, b.y);
        }
    }
}

__device__ __forceinline__ void add_bias_relu(const float* __restrict__ sb,
                                              int t, float c[16][4], bool do_relu)
{
#pragma unroll
    for (int nb = 0; nb < 16; nb++) {
        float bx = sb[nb * 8 + 2 * t], by = sb[nb * 8 + 2 * t + 1];
        c[nb][0] += bx; c[nb][1] += by; c[nb][2] += bx; c[nb][3] += by;
        if (do_relu) {
            c[nb][0] = fmaxf(c[nb][0], 0.f); c[nb][1] = fmaxf(c[nb][1], 0.f);
            c[nb][2] = fmaxf(c[nb][2], 0.f); c[nb][3] = fmaxf(c[nb][3], 0.f);
        }
    }
}

// Convert fp32 accumulators -> next-stage fp16 A fragments (pure register op:
// C frag layout of two adjacent n8 blocks == A frag layout of one k16 block).
__device__ __forceinline__ void acc_to_afrag(const float c[16][4], unsigned a[8][4])
{
#pragma unroll
    for (int kb = 0; kb < 8; kb++) {
        a[kb][0] = pack_h2(c[2 * kb][0],     c[2 * kb][1]);
        a[kb][1] = pack_h2(c[2 * kb][2],     c[2 * kb][3]);
        a[kb][2] = pack_h2(c[2 * kb + 1][0], c[2 * kb + 1][1]);
        a[kb][3] = pack_h2(c[2 * kb + 1][2], c[2 * kb + 1][3]);
    }
}

__global__ void __launch_bounds__(256, 1)
fused_kernel(const float* __restrict__ tf, float* __restrict__ out)
{
    extern __shared__ unsigned char smem[];
    uint2* sFrag = reinterpret_cast<uint2*>(smem);
    float* sBias = reinterpret_cast<float*>(smem + SMEM_FRAG_BYTES);

    // One-time weight staging (persistent CTA)
    {
        const uint4* src = reinterpret_cast<const uint4*>(g_frag);
        uint4* dst = reinterpret_cast<uint4*>(smem);
        for (int i = threadIdx.x; i < SMEM_FRAG_BYTES / 16; i += 256) dst[i] = src[i];
        const float* bs = &g_bias[0][0];
        for (int i = threadIdx.x; i < N_STAGES * DIM; i += 256) sBias[i] = bs[i];
    }
    __syncthreads();

    const int warp = threadIdx.x >> 5, lane = threadIdx.x & 31;
    const int g = lane >> 2, t = lane & 3;

    for (int tile = blockIdx.x; tile < N_TILES; tile += gridDim.x) {
        const int r0 = tile * 128 + warp * 16 + g;   // rows r0 and r0+8
        const float* p0 = tf + (size_t)r0 * DIM;
        const float* p1 = p0 + 8 * DIM;

        // ---- Stage 0 A fragments straight from gmem (fp32 -> fp16) ----
        unsigned frX[8][4];
#pragma unroll
        for (int kb = 0; kb < 8; kb++) {
            float2 x0 = *reinterpret_cast<const float2*>(p0 + kb * 16 + 2 * t);
            float2 x1 = *reinterpret_cast<const float2*>(p1 + kb * 16 + 2 * t);
            float2 x2 = *reinterpret_cast<const float2*>(p0 + kb * 16 + 8 + 2 * t);
            float2 x3 = *reinterpret_cast<const float2*>(p1 + kb * 16 + 8 + 2 * t);
            frX[kb][0] = pack_h2(x0.x, x0.y);
            frX[kb][1] = pack_h2(x1.x, x1.y);
            frX[kb][2] = pack_h2(x2.x, x2.y);
            frX[kb][3] = pack_h2(x3.x, x3.y);
        }

        // ---- Stage 0: A = tf @ Wc^T + bc ----
        float accA[16][4];
#pragma unroll
        for (int nb = 0; nb < 16; nb++)
            accA[nb][0] = accA[nb][1] = accA[nb][2] = accA[nb][3] = 0.f;
        run_gemm(sFrag, 0, lane, frX, accA);
        add_bias_relu(sBias + 0 * DIM, t, accA, false);

        // ---- Stage 1: h = relu(A @ W1eff^T + b1) ----
        unsigned frA[8][4];
        acc_to_afrag(accA, frA);          // accA kept: fp32 residual for stage 2
        float accH[16][4];
#pragma unroll
        for (int nb = 0; nb < 16; nb++)
            accH[nb][0] = accH[nb][1] = accH[nb][2] = accH[nb][3] = 0.f;
        run_gemm(sFrag, 1, lane, frA, accH);
        add_bias_relu(sBias + 1 * DIM, t, accH, true);

        // ---- Stage 2: Ahat = h @ W2^T + b2 + A (accumulate into residual) ----
        acc_to_afrag(accH, frX);          // frX := h fragments
        add_bias_relu(sBias + 2 * DIM, t, accA, false);   // accA := A + b2
        run_gemm(sFrag, 2, lane, frX, accA);              // accA := Ahat

        // ---- Stage 3: h2 = relu(Ahat @ W3^T + b3) ----
        acc_to_afrag(accA, frA);          // frA := Ahat fragments
#pragma unroll
        for (int nb = 0; nb < 16; nb++)
            accH[nb][0] = accH[nb][1] = accH[nb][2] = accH[nb][3] = 0.f;
        run_gemm(sFrag, 3, lane, frA, accH);
        add_bias_relu(sBias + 3 * DIM, t, accH, true);

        // ---- Stage 4: out = h2 @ W4^T + b4 + tf (residual from gmem, fp32) ----
        acc_to_afrag(accH, frX);          // frX := h2 fragments
        const float* sb4 = sBias + 4 * DIM;
#pragma unroll
        for (int nb = 0; nb < 16; nb++) {
            float2 q0 = *reinterpret_cast<const float2*>(p0 + nb * 8 + 2 * t);
            float2 q1 = *reinterpret_cast<const float2*>(p1 + nb * 8 + 2 * t);
            float bx = sb4[nb * 8 + 2 * t], by = sb4[nb * 8 + 2 * t + 1];
            accA[nb][0] = q0.x + bx; accA[nb][1] = q0.y + by;
            accA[nb][2] = q1.x + bx; accA[nb][3] = q1.y + by;
        }
        run_gemm(sFrag, 4, lane, frX, accA);

        // ---- Store ----
        float* o0 = out + (size_t)r0 * DIM;
        float* o1 = o0 + 8 * DIM;
#pragma unroll
        for (int nb = 0; nb < 16; nb++) {
            *reinterpret_cast<float2*>(o0 + nb * 8 + 2 * t) =
                make_float2(accA[nb][0], accA[nb][1]);
            *reinterpret_cast<float2*>(o1 + nb * 8 + 2 * t) =
                make_float2(accA[nb][2], accA[nb][3]);
        }
    }
}

// ----------------------------------------------------------------------------
extern "C" void kernel_launch(void* const* d_in, const int* in_sizes, int n_in,
                              void* d_out, int out_size)
{
    const float* tf   = (const float*)d_in[0];
    const float* ipw  = (const float*)d_in[1];
    const float* ipb  = (const float*)d_in[2];
    const float* ow   = (const float*)d_in[3];
    const float* ob   = (const float*)d_in[4];
    const float* fw1  = (const float*)d_in[5];
    const float* fb1  = (const float*)d_in[6];
    const float* fw2  = (const float*)d_in[7];
    const float* fb2  = (const float*)d_in[8];
    const float* uw1  = (const float*)d_in[9];
    const float* ub1  = (const float*)d_in[10];
    const float* uw2  = (const float*)d_in[11];
    const float* ub2  = (const float*)d_in[12];

    precompute_dense<<<dim3(128, 5), 128>>>(ipw, ipb, ow, ob, fw1, fb1,
                                            fw2, fb2, uw1, ub1, uw2, ub2);
    pack_frags<<<80, 256>>>();

    cudaFuncSetAttribute(fused_kernel,
                         cudaFuncAttributeMaxDynamicSharedMemorySize, SMEM_TOTAL);
    fused_kernel<<<GRID_MAIN, 256, SMEM_TOTAL>>>(tf, (float*)d_out);
}

// round 7
// speedup vs baseline: 1.0527x; 1.0527x over previous
#include <cuda_runtime.h>
#include <cuda_fp16.h>
#include <cstdint>

// ============================================================================
// FeatureSharingLayer: 5 chained 128x128 GEMMs over M = 262144 rows.
// mma.sync m16n8k16 fp16 (fp32 accum). Weights folded + packed as B-fragment
// uint4 pairs (one LDS.128 feeds two MMAs). Bias folded into accumulator init.
// Residual A carried as fp16 fragments (same regs that feed stage 1).
// ============================================================================

#define DIM 128
#define M_TOTAL (32768 * 8)      // 262144
#define N_TILES (M_TOTAL / 128)  // 2048
#define N_STAGES 5
#define GRID_MAIN 152
#define THREADS 256

// packed B fragments: [stage][kb(8)][nbp(8)][lane(32)] -> uint4
//   .x,.y = frag regs of nb=2*nbp ; .z,.w = frag regs of nb=2*nbp+1
__device__ uint4 g_fragB[N_STAGES * 8 * 8 * 32];
__device__ float g_bias[N_STAGES][DIM];

#define SMEM_FRAG_BYTES (N_STAGES * 8 * 8 * 32 * 16)      // 163840
#define SMEM_BIAS_BYTES (N_STAGES * DIM * 4)              // 2560
#define SMEM_TOTAL (SMEM_FRAG_BYTES + SMEM_BIAS_BYTES)

// ----------------------------------------------------------------------------
// Prologue: fold weights, convert fp16, scatter into B-fragment layout.
// grid (128, 5), block 128.  blockIdx.x = n, blockIdx.y = stage, tid = k.
// Fragment element for (n,k): lane = (n&7)*4 + ((k&7)>>1)
//   uint4 idx = ((s*8 + k>>4)*8 + (n>>4))*32 + lane
//   half slot  = (n>>3 & 1)*4 + ((k>>3)&1)*2 + (k&1)
// ----------------------------------------------------------------------------
__global__ void precompute_pack(
    const float* __restrict__ ipw, const float* __restrict__ ipb,
    const float* __restrict__ ow,  const float* __restrict__ ob,
    const float* __restrict__ fw1, const float* __restrict__ fb1,
    const float* __restrict__ fw2, const float* __restrict__ fb2,
    const float* __restrict__ uw1, const float* __restrict__ ub1,
    const float* __restrict__ uw2, const float* __restrict__ ub2)
{
    const int n = blockIdx.x, s = blockIdx.y, k = threadIdx.x;
    __shared__ float srow[DIM];

    float v = 0.f;
    if (s == 0) {
        srow[k] = ow[n * DIM + k];
        __syncthreads();
#pragma unroll 8
        for (int j = 0; j < DIM; j++)
            v += srow[j] * ipw[(256 + j) * DIM + k];
    } else if (s == 1) {
#pragma unroll
        for (int t = 0; t < 8; t++) v += fw1[n * 1024 + t * DIM + k];
    } else if (s == 2) v = fw2[n * DIM + k];
    else if (s == 3)   v = uw1[n * DIM + k];
    else               v = uw2[n * DIM + k];

    {
        const int lane = (n & 7) * 4 + ((k & 7) >> 1);
        const int idx4 = ((s * 8 + (k >> 4)) * 8 + (n >> 4)) * 32 + lane;
        const int slot = ((n >> 3) & 1) * 4 + ((k >> 3) & 1) * 2 + (k & 1);
        reinterpret_cast<__half*>(g_fragB)[idx4 * 8 + slot] = __float2half(v);
    }

    if (k == 0) {
        float b;
        if (s == 0) {
            b = ob[n];
            for (int j = 0; j < DIM; j++) b += ow[n * DIM + j] * ipb[256 + j];
        } else if (s == 1) b = fb1[n];
        else if (s == 2)   b = fb2[n];
        else if (s == 3)   b = ub1[n];
        else               b = ub2[n];
        g_bias[s][n] = b;
    }
}

// ----------------------------------------------------------------------------
// Device helpers
// ----------------------------------------------------------------------------
__device__ __forceinline__ unsigned pack_h2(float x, float y)
{
    __half2 h = __floats2half2_rn(x, y);
    return *reinterpret_cast<unsigned*>(&h);
}

__device__ __forceinline__ void mma16816(float c[4], const unsigned a[4],
                                         unsigned b0, unsigned b1)
{
    asm volatile(
        "mma.sync.aligned.m16n8k16.row.col.f32.f16.f16.f32 "
        "{%0,%1,%2,%3}, {%4,%5,%6,%7}, {%8,%9}, {%0,%1,%2,%3};\n"
        : "+f"(c[0]), "+f"(c[1]), "+f"(c[2]), "+f"(c[3])
        : "r"(a[0]), "r"(a[1]), "r"(a[2]), "r"(a[3]), "r"(b0), "r"(b1));
}

// full 16x128 x 128x128 GEMM for this warp; B via LDS.128 pairs
__device__ __forceinline__ void run_gemm(const uint4* __restrict__ sFrag, int s,
                                         int lane, const unsigned a[8][4],
                                         float c[16][4])
{
#pragma unroll
    for (int kb = 0; kb < 8; kb++) {
        const uint4* bp = sFrag + ((s * 8 + kb) * 8) * 32 + lane;
#pragma unroll
        for (int p = 0; p < 8; p++) {
            uint4 b = bp[p * 32];
            mma16816(c[2 * p],     a[kb], b.x, b.y);
            mma16816(c[2 * p + 1], a[kb], b.z, b.w);
        }
    }
}

// init accumulators with per-column bias
__device__ __forceinline__ void bias_init(const float* __restrict__ sb, int s,
                                          int t, float c[16][4])
{
    const float2* bp = reinterpret_cast<const float2*>(sb + s * DIM + 2 * t);
#pragma unroll
    for (int nb = 0; nb < 16; nb++) {
        float2 b = bp[nb * 4];          // sb[s*128 + nb*8 + 2t]
        c[nb][0] = b.x; c[nb][1] = b.y; c[nb][2] = b.x; c[nb][3] = b.y;
    }
}

__device__ __forceinline__ void do_relu(float c[16][4])
{
#pragma unroll
    for (int nb = 0; nb < 16; nb++) {
        c[nb][0] = fmaxf(c[nb][0], 0.f); c[nb][1] = fmaxf(c[nb][1], 0.f);
        c[nb][2] = fmaxf(c[nb][2], 0.f); c[nb][3] = fmaxf(c[nb][3], 0.f);
    }
}

// fp32 accumulators -> fp16 A fragments for the next stage (register-only)
__device__ __forceinline__ void acc_to_afrag(const float c[16][4], unsigned a[8][4])
{
#pragma unroll
    for (int kb = 0; kb < 8; kb++) {
        a[kb][0] = pack_h2(c[2 * kb][0],     c[2 * kb][1]);
        a[kb][1] = pack_h2(c[2 * kb][2],     c[2 * kb][3]);
        a[kb][2] = pack_h2(c[2 * kb + 1][0], c[2 * kb + 1][1]);
        a[kb][3] = pack_h2(c[2 * kb + 1][2], c[2 * kb + 1][3]);
    }
}

// add fp16 A fragments into fp32 accumulators (stage-2 residual)
__device__ __forceinline__ void add_afrag(float c[16][4], const unsigned a[8][4])
{
#pragma unroll
    for (int kb = 0; kb < 8; kb++) {
        float2 f0 = __half22float2(*reinterpret_cast<const __half2*>(&a[kb][0]));
        float2 f1 = __half22float2(*reinterpret_cast<const __half2*>(&a[kb][1]));
        float2 f2 = __half22float2(*reinterpret_cast<const __half2*>(&a[kb][2]));
        float2 f3 = __half22float2(*reinterpret_cast<const __half2*>(&a[kb][3]));
        c[2 * kb][0]     += f0.x; c[2 * kb][1]     += f0.y;
        c[2 * kb][2]     += f1.x; c[2 * kb][3]     += f1.y;
        c[2 * kb + 1][0] += f2.x; c[2 * kb + 1][1] += f2.y;
        c[2 * kb + 1][2] += f3.x; c[2 * kb + 1][3] += f3.y;
    }
}

// ----------------------------------------------------------------------------
// Main fused kernel (persistent)
// ----------------------------------------------------------------------------
__global__ void __launch_bounds__(THREADS, 1)
fused_kernel(const float* __restrict__ tf, float* __restrict__ out)
{
    extern __shared__ unsigned char smem[];
    uint4* sFrag = reinterpret_cast<uint4*>(smem);
    float* sBias = reinterpret_cast<float*>(smem + SMEM_FRAG_BYTES);

    {   // one-time weight staging
        const uint4* src = g_fragB;
        for (int i = threadIdx.x; i < SMEM_FRAG_BYTES / 16; i += THREADS)
            sFrag[i] = src[i];
        const float* bs = &g_bias[0][0];
        for (int i = threadIdx.x; i < N_STAGES * DIM; i += THREADS)
            sBias[i] = bs[i];
    }
    __syncthreads();

    const int warp = threadIdx.x >> 5, lane = threadIdx.x & 31;
    const int g = lane >> 2, t = lane & 3;

    for (int tile = blockIdx.x; tile < N_TILES; tile += GRID_MAIN) {
        const int r0 = tile * 128 + warp * 16 + g;   // rows r0, r0+8
        const float* p0 = tf + (size_t)r0 * DIM;
        const float* p1 = p0 + 8 * DIM;

        // ---- stage-0 A fragments straight from gmem ----
        unsigned frX[8][4];
#pragma unroll
        for (int kb = 0; kb < 8; kb++) {
            float2 x0 = *reinterpret_cast<const float2*>(p0 + kb * 16 + 2 * t);
            float2 x1 = *reinterpret_cast<const float2*>(p1 + kb * 16 + 2 * t);
            float2 x2 = *reinterpret_cast<const float2*>(p0 + kb * 16 + 8 + 2 * t);
            float2 x3 = *reinterpret_cast<const float2*>(p1 + kb * 16 + 8 + 2 * t);
            frX[kb][0] = pack_h2(x0.x, x0.y);
            frX[kb][1] = pack_h2(x1.x, x1.y);
            frX[kb][2] = pack_h2(x2.x, x2.y);
            frX[kb][3] = pack_h2(x3.x, x3.y);
        }

        float acc[16][4];

        // ---- S0: A = tf @ Wc^T + bc ----
        bias_init(sBias, 0, t, acc);
        run_gemm(sFrag, 0, lane, frX, acc);

        // frA doubles as stage-1 input AND fp16 residual for stage 2
        unsigned frA[8][4];
        acc_to_afrag(acc, frA);

        // ---- S1: h = relu(A @ W1eff^T + b1) ----
        bias_init(sBias, 1, t, acc);
        run_gemm(sFrag, 1, lane, frA, acc);
        do_relu(acc);
        acc_to_afrag(acc, frX);          // frX := h

        // ---- S2: Ahat = h @ W2^T + b2 + A ----
        bias_init(sBias, 2, t, acc);
        add_afrag(acc, frA);             // + residual A (fp16)
        run_gemm(sFrag, 2, lane, frX, acc);
        acc_to_afrag(acc, frA);          // frA := Ahat

        // ---- S3: h2 = relu(Ahat @ W3^T + b3) ----
        bias_init(sBias, 3, t, acc);
        run_gemm(sFrag, 3, lane, frA, acc);
        do_relu(acc);
        acc_to_afrag(acc, frX);          // frX := h2

        // ---- S4: out = h2 @ W4^T + b4 + tf (exact fp32 residual) ----
        {
            const float2* bp = reinterpret_cast<const float2*>(sBias + 4 * DIM + 2 * t);
#pragma unroll
            for (int nb = 0; nb < 16; nb++) {
                float2 q0 = *reinterpret_cast<const float2*>(p0 + nb * 8 + 2 * t);
                float2 q1 = *reinterpret_cast<const float2*>(p1 + nb * 8 + 2 * t);
                float2 b = bp[nb * 4];
                acc[nb][0] = q0.x + b.x; acc[nb][1] = q0.y + b.y;
                acc[nb][2] = q1.x + b.x; acc[nb][3] = q1.y + b.y;
            }
        }
        run_gemm(sFrag, 4, lane, frX, acc);

        // ---- store ----
        float* o0 = out + (size_t)r0 * DIM;
        float* o1 = o0 + 8 * DIM;
#pragma unroll
        for (int nb = 0; nb < 16; nb++) {
            *reinterpret_cast<float2*>(o0 + nb * 8 + 2 * t) =
                make_float2(acc[nb][0], acc[nb][1]);
            *reinterpret_cast<float2*>(o1 + nb * 8 + 2 * t) =
                make_float2(acc[nb][2], acc[nb][3]);
        }
    }
}

// ----------------------------------------------------------------------------
extern "C" void kernel_launch(void* const* d_in, const int* in_sizes, int n_in,
                              void* d_out, int out_size)
{
    const float* tf  = (const float*)d_in[0];
    const float* ipw = (const float*)d_in[1];
    const float* ipb = (const float*)d_in[2];
    const float* ow  = (const float*)d_in[3];
    const float* ob  = (const float*)d_in[4];
    const float* fw1 = (const float*)d_in[5];
    const float* fb1 = (const float*)d_in[6];
    const float* fw2 = (const float*)d_in[7];
    const float* fb2 = (const float*)d_in[8];
    const float* uw1 = (const float*)d_in[9];
    const float* ub1 = (const float*)d_in[10];
    const float* uw2 = (const float*)d_in[11];
    const float* ub2 = (const float*)d_in[12];

    precompute_pack<<<dim3(128, 5), 128>>>(ipw, ipb, ow, ob, fw1, fb1,
                                           fw2, fb2, uw1, ub1, uw2, ub2);

    cudaFuncSetAttribute(fused_kernel,
                         cudaFuncAttributeMaxDynamicSharedMemorySize, SMEM_TOTAL);
    fused_kernel<<<GRID_MAIN, THREADS, SMEM_TOTAL>>>(tf, (float*)d_out);
}